// round 1
// baseline (speedup 1.0000x reference)
#include <cuda_runtime.h>

// ---------------------------------------------------------------------------
// 2-layer LSTM (H=4, I=2, T=50) + readout, one thread per batch element.
// Split into two kernels (layer0 / layer1+readout) because the full weight set
// (256 floats) exceeds the 255-register cap; h0 sequence round-trips through a
// static __device__ scratch in [T][B][4] layout (coalesced float4 both ways).
// Gate math uses packed fp32x2 FFMA (fma.rn.f32x2, sm_100+) for 2x FMA tput.
// Activations use ex2.approx + rcp.approx (~1e-7 err) to stay well inside the
// 1e-3 rel-err budget over 50 recurrent steps.
// ---------------------------------------------------------------------------

#define T_STEPS 50
#define B_MAX   262144
typedef unsigned long long ull;

// h0 scratch: [T][B][H] as float4 per (t,b). 50*262144*16B = 200 MB.
__device__ float4 g_h0[(size_t)T_STEPS * B_MAX];

__device__ __forceinline__ ull pk2(float lo, float hi) {
    ull r; asm("mov.b64 %0, {%1, %2};" : "=l"(r) : "f"(lo), "f"(hi)); return r;
}
__device__ __forceinline__ void upk2(ull v, float& lo, float& hi) {
    asm("mov.b64 {%0, %1}, %2;" : "=f"(lo), "=f"(hi) : "l"(v));
}
__device__ __forceinline__ ull ffma2(ull a, ull b, ull c) {
    ull d; asm("fma.rn.f32x2 %0, %1, %2, %3;" : "=l"(d) : "l"(a), "l"(b), "l"(c));
    return d;
}
__device__ __forceinline__ float ex2f(float x) {
    float r; asm("ex2.approx.f32 %0, %1;" : "=f"(r) : "f"(x)); return r;
}
__device__ __forceinline__ float rcpf(float x) {
    float r; asm("rcp.approx.f32 %0, %1;" : "=f"(r) : "f"(x)); return r;
}
// sigmoid(x) = 1/(1+exp(-x)); exp(-x) = 2^(-x*log2(e))
__device__ __forceinline__ float sigf(float x) {
    return rcpf(1.0f + ex2f(-1.442695040888963f * x));
}
// tanh(x) = 1 - 2/(1+exp(2x))
__device__ __forceinline__ float tanh_f(float x) {
    return 1.0f - 2.0f * rcpf(1.0f + ex2f(2.885390081777927f * x));
}

// ---------------------------------------------------------------------------
// Kernel A: layer 0.  x:[B,T,2] row-major -> h0 scratch [T][B][4]
// ---------------------------------------------------------------------------
__global__ __launch_bounds__(128, 3) void lstm_l0(
    const float* __restrict__ x,
    const float* __restrict__ Wih,  // [16, 2]
    const float* __restrict__ Whh,  // [16, 4]
    const float* __restrict__ bih,  // [16]
    const float* __restrict__ bhh,  // [16]
    int B)
{
    int b = blockIdx.x * 128 + threadIdx.x;
    if (b >= B) return;

    // Pack weights as gate-pairs: pair p covers gates (2p, 2p+1).
    ull wi[8][2], wh[8][4], bs[8];
#pragma unroll
    for (int p = 0; p < 8; p++) {
#pragma unroll
        for (int j = 0; j < 2; j++)
            wi[p][j] = pk2(__ldg(&Wih[(2 * p) * 2 + j]), __ldg(&Wih[(2 * p + 1) * 2 + j]));
#pragma unroll
        for (int k = 0; k < 4; k++)
            wh[p][k] = pk2(__ldg(&Whh[(2 * p) * 4 + k]), __ldg(&Whh[(2 * p + 1) * 4 + k]));
        bs[p] = pk2(__ldg(&bih[2 * p])     + __ldg(&bhh[2 * p]),
                    __ldg(&bih[2 * p + 1]) + __ldg(&bhh[2 * p + 1]));
    }

    float h0v = 0.f, h1v = 0.f, h2v = 0.f, h3v = 0.f;
    float c0 = 0.f, c1 = 0.f, c2 = 0.f, c3 = 0.f;

    const float4* xb   = reinterpret_cast<const float4*>(x + (size_t)b * (T_STEPS * 2));
    float4*       outp = g_h0 + b;

#pragma unroll 1
    for (int tt = 0; tt < T_STEPS / 2; ++tt) {
        float4 xv = __ldg(&xb[tt]);   // two timesteps of (x0, x1)
#pragma unroll
        for (int s = 0; s < 2; s++) {
            float x0 = s ? xv.z : xv.x;
            float x1 = s ? xv.w : xv.y;
            ull d0  = pk2(x0, x0),   d1  = pk2(x1, x1);
            ull dh0 = pk2(h0v, h0v), dh1 = pk2(h1v, h1v);
            ull dh2 = pk2(h2v, h2v), dh3 = pk2(h3v, h3v);

            ull acc[8];
#pragma unroll
            for (int p = 0; p < 8; p++) {
                ull a = ffma2(wi[p][0], d0, bs[p]);
                a = ffma2(wi[p][1], d1, a);
                a = ffma2(wh[p][0], dh0, a);
                a = ffma2(wh[p][1], dh1, a);
                a = ffma2(wh[p][2], dh2, a);
                a = ffma2(wh[p][3], dh3, a);
                acc[p] = a;
            }
            float g[16];
#pragma unroll
            for (int p = 0; p < 8; p++) upk2(acc[p], g[2 * p], g[2 * p + 1]);

            // PyTorch gate order: [0..3]=i, [4..7]=f, [8..11]=g, [12..15]=o
            c0 = sigf(g[4]) * c0 + sigf(g[0]) * tanh_f(g[8]);
            c1 = sigf(g[5]) * c1 + sigf(g[1]) * tanh_f(g[9]);
            c2 = sigf(g[6]) * c2 + sigf(g[2]) * tanh_f(g[10]);
            c3 = sigf(g[7]) * c3 + sigf(g[3]) * tanh_f(g[11]);
            h0v = sigf(g[12]) * tanh_f(c0);
            h1v = sigf(g[13]) * tanh_f(c1);
            h2v = sigf(g[14]) * tanh_f(c2);
            h3v = sigf(g[15]) * tanh_f(c3);

            *outp = make_float4(h0v, h1v, h2v, h3v);
            outp += B;
        }
    }
}

// ---------------------------------------------------------------------------
// Kernel B: layer 1 + fused readout.  h0 scratch -> out[b] = sigmoid(z)
// ---------------------------------------------------------------------------
__global__ __launch_bounds__(128, 2) void lstm_l1(
    const float* __restrict__ Wih,   // [16, 4]
    const float* __restrict__ Whh,   // [16, 4]
    const float* __restrict__ bih,
    const float* __restrict__ bhh,
    const float* __restrict__ Wout,  // [1, 200], col index = t*4 + k
    const float* __restrict__ bout,  // [1]
    float* __restrict__ out,
    int B)
{
    int b = blockIdx.x * 128 + threadIdx.x;
    if (b >= B) return;

    ull wi[8][4], wh[8][4], bs[8];
#pragma unroll
    for (int p = 0; p < 8; p++) {
#pragma unroll
        for (int k = 0; k < 4; k++) {
            wi[p][k] = pk2(__ldg(&Wih[(2 * p) * 4 + k]), __ldg(&Wih[(2 * p + 1) * 4 + k]));
            wh[p][k] = pk2(__ldg(&Whh[(2 * p) * 4 + k]), __ldg(&Whh[(2 * p + 1) * 4 + k]));
        }
        bs[p] = pk2(__ldg(&bih[2 * p])     + __ldg(&bhh[2 * p]),
                    __ldg(&bih[2 * p + 1]) + __ldg(&bhh[2 * p + 1]));
    }

    float h0v = 0.f, h1v = 0.f, h2v = 0.f, h3v = 0.f;
    float c0 = 0.f, c1 = 0.f, c2 = 0.f, c3 = 0.f;
    float z = __ldg(&bout[0]);

    const float4* hp  = g_h0 + b;
    const float4* wo4 = reinterpret_cast<const float4*>(Wout);

    float4 hin = __ldg(&hp[0]);
#pragma unroll 1
    for (int t = 0; t < T_STEPS; t++) {
        // prefetch next step's h0 one iteration ahead (hides DRAM latency)
        float4 hnx = (t + 1 < T_STEPS) ? __ldg(&hp[(size_t)(t + 1) * B])
                                       : make_float4(0.f, 0.f, 0.f, 0.f);

        ull d0  = pk2(hin.x, hin.x), d1  = pk2(hin.y, hin.y);
        ull d2  = pk2(hin.z, hin.z), d3  = pk2(hin.w, hin.w);
        ull dh0 = pk2(h0v, h0v), dh1 = pk2(h1v, h1v);
        ull dh2 = pk2(h2v, h2v), dh3 = pk2(h3v, h3v);

        ull acc[8];
#pragma unroll
        for (int p = 0; p < 8; p++) {
            ull a = ffma2(wi[p][0], d0, bs[p]);
            a = ffma2(wi[p][1], d1, a);
            a = ffma2(wi[p][2], d2, a);
            a = ffma2(wi[p][3], d3, a);
            a = ffma2(wh[p][0], dh0, a);
            a = ffma2(wh[p][1], dh1, a);
            a = ffma2(wh[p][2], dh2, a);
            a = ffma2(wh[p][3], dh3, a);
            acc[p] = a;
        }
        float g[16];
#pragma unroll
        for (int p = 0; p < 8; p++) upk2(acc[p], g[2 * p], g[2 * p + 1]);

        c0 = sigf(g[4]) * c0 + sigf(g[0]) * tanh_f(g[8]);
        c1 = sigf(g[5]) * c1 + sigf(g[1]) * tanh_f(g[9]);
        c2 = sigf(g[6]) * c2 + sigf(g[2]) * tanh_f(g[10]);
        c3 = sigf(g[7]) * c3 + sigf(g[3]) * tanh_f(g[11]);
        h0v = sigf(g[12]) * tanh_f(c0);
        h1v = sigf(g[13]) * tanh_f(c1);
        h2v = sigf(g[14]) * tanh_f(c2);
        h3v = sigf(g[15]) * tanh_f(c3);

        // fused readout: z += h1_t . Wout[:, t*4 .. t*4+3]  (uniform broadcast load)
        float4 w = __ldg(&wo4[t]);
        z = fmaf(h0v, w.x, z);
        z = fmaf(h1v, w.y, z);
        z = fmaf(h2v, w.z, z);
        z = fmaf(h3v, w.w, z);

        hin = hnx;
    }

    out[b] = rcpf(1.0f + ex2f(-1.442695040888963f * z));
}

// ---------------------------------------------------------------------------
// Launch: inputs per metadata order:
// x, Wih0, Whh0, bih0, bhh0, Wih1, Whh1, bih1, bhh1, Wout, bout
// ---------------------------------------------------------------------------
extern "C" void kernel_launch(void* const* d_in, const int* in_sizes, int n_in,
                              void* d_out, int out_size)
{
    const float* x    = (const float*)d_in[0];
    const float* Wih0 = (const float*)d_in[1];
    const float* Whh0 = (const float*)d_in[2];
    const float* bih0 = (const float*)d_in[3];
    const float* bhh0 = (const float*)d_in[4];
    const float* Wih1 = (const float*)d_in[5];
    const float* Whh1 = (const float*)d_in[6];
    const float* bih1 = (const float*)d_in[7];
    const float* bhh1 = (const float*)d_in[8];
    const float* Wout = (const float*)d_in[9];
    const float* bout = (const float*)d_in[10];

    int B = in_sizes[0] / (T_STEPS * 2);
    if (B > B_MAX) B = B_MAX;
    int grid = (B + 127) / 128;

    lstm_l0<<<grid, 128>>>(x, Wih0, Whh0, bih0, bhh0, B);
    lstm_l1<<<grid, 128>>>(Wih1, Whh1, bih1, bhh1, Wout, bout, (float*)d_out, B);
}

// round 2
// speedup vs baseline: 1.0642x; 1.0642x over previous
#include <cuda_runtime.h>

// ---------------------------------------------------------------------------
// 2-layer LSTM (H=4, I=2, T=50) + readout.
// R2: TWO threads per batch element (thread half h owns hidden units 2h,2h+1,
// i.e. 8 of the 16 gate rows). Halves the register-resident weight footprint
// (the R1 occupancy killer: 197 regs -> 12% occ) so we reach 4-5 blocks/SM.
// Partner h-values exchanged with 2x shfl.xor per step.
// Activation scale factors (-log2e for sigmoid gates, +2log2e for the g gate)
// are folded into the weights at prologue. Reciprocals are computed in pairs
// (1 rcp + 3 mul replaces 2 rcp) cutting MUFU pressure 25%.
// Gate MACs use packed fma.rn.f32x2 (gate-pair per 64-bit register).
// ---------------------------------------------------------------------------

#define T_STEPS 50
#define B_MAX   262144
typedef unsigned long long ull;

#define SIG_S  (-1.442695040888963f)   // -log2(e): sigmoid gates i,f,o
#define TANH_S ( 2.885390081777927f)   // +2*log2(e): tanh gate g and tanh(c)

// h0 scratch: [T][B] float4. 50*262144*16B = 200 MB.
__device__ float4 g_h0[(size_t)T_STEPS * B_MAX];

__device__ __forceinline__ ull pk2(float lo, float hi) {
    ull r; asm("mov.b64 %0, {%1, %2};" : "=l"(r) : "f"(lo), "f"(hi)); return r;
}
__device__ __forceinline__ void upk2(ull v, float& lo, float& hi) {
    asm("mov.b64 {%0, %1}, %2;" : "=f"(lo), "=f"(hi) : "l"(v));
}
__device__ __forceinline__ ull ffma2(ull a, ull b, ull c) {
    ull d; asm("fma.rn.f32x2 %0, %1, %2, %3;" : "=l"(d) : "l"(a), "l"(b), "l"(c));
    return d;
}
__device__ __forceinline__ float ex2f(float x) {
    float r; asm("ex2.approx.f32 %0, %1;" : "=f"(r) : "f"(x)); return r;
}
__device__ __forceinline__ float rcpf(float x) {
    float r; asm("rcp.approx.f32 %0, %1;" : "=f"(r) : "f"(x)); return r;
}
__device__ __forceinline__ float sigf(float x) {   // accurate sigmoid (final out)
    return rcpf(1.0f + ex2f(SIG_S * x));
}

// Gate row bases in PyTorch order (i, f, g, o) and per-class folded scale.
__device__ __forceinline__ float gate_scale(int G) { return (G == 2) ? TANH_S : SIG_S; }
__constant__ int c_dummy; // (unused; keeps nvcc happy about empty const seg)

// ---------------------------------------------------------------------------
// Shared per-step activation block: y[0..7] = scaled gate pre-acts for this
// thread's 2 units (i0,i1,f0,f1,g0,g1,o0,o1). Updates c0,c1; returns hA,hB.
// ---------------------------------------------------------------------------
__device__ __forceinline__ void lstm_act(
    const float* y, float& c0, float& c1, float& hA, float& hB)
{
    float a0 = 1.f + ex2f(y[0]);
    float a1 = 1.f + ex2f(y[1]);
    float a2 = 1.f + ex2f(y[2]);
    float a3 = 1.f + ex2f(y[3]);
    float a4 = 1.f + ex2f(y[4]);
    float a5 = 1.f + ex2f(y[5]);
    float a6 = 1.f + ex2f(y[6]);
    float a7 = 1.f + ex2f(y[7]);

    float pi_ = rcpf(a0 * a1);           // sigmoid(i) pair
    float si0 = pi_ * a1, si1 = pi_ * a0;
    float pf_ = rcpf(a2 * a3);           // sigmoid(f) pair
    float sf0 = pf_ * a3, sf1 = pf_ * a2;
    float pg_ = rcpf(a4 * a5);           // tanh(g) pair
    float tg0 = fmaf(-2.f, pg_ * a5, 1.f);
    float tg1 = fmaf(-2.f, pg_ * a4, 1.f);
    float po_ = rcpf(a6 * a7);           // sigmoid(o) pair
    float so0 = po_ * a7, so1 = po_ * a6;

    c0 = fmaf(sf0, c0, si0 * tg0);
    c1 = fmaf(sf1, c1, si1 * tg1);

    float ac0 = 1.f + ex2f(TANH_S * c0);
    float ac1 = 1.f + ex2f(TANH_S * c1);
    float pc_ = rcpf(ac0 * ac1);         // tanh(c) pair
    float tc0 = fmaf(-2.f, pc_ * ac1, 1.f);
    float tc1 = fmaf(-2.f, pc_ * ac0, 1.f);

    hA = so0 * tc0;
    hB = so1 * tc1;
}

// ---------------------------------------------------------------------------
// Kernel A: layer 0.  x:[B,T,2] -> h0 scratch [T][B] float4.
// ---------------------------------------------------------------------------
__global__ __launch_bounds__(128, 5) void lstm_l0(
    const float* __restrict__ x,
    const float* __restrict__ Wih,  // [16, 2]
    const float* __restrict__ Whh,  // [16, 4]
    const float* __restrict__ bih,
    const float* __restrict__ bhh,
    int B)
{
    int g    = blockIdx.x * 128 + threadIdx.x;
    int b    = g >> 1;
    int half = g & 1;
    if (b >= B) return;

    // This thread's 2 gate rows per class: base + 2*half (+0/+1).
    ull wi[4][2], wh[4][4], bs[4];
#pragma unroll
    for (int G = 0; G < 4; G++) {
        int r0 = G * 4 + 2 * half;
        float s = gate_scale(G);
#pragma unroll
        for (int k = 0; k < 2; k++)
            wi[G][k] = pk2(s * __ldg(&Wih[r0 * 2 + k]), s * __ldg(&Wih[(r0 + 1) * 2 + k]));
#pragma unroll
        for (int k = 0; k < 4; k++)
            wh[G][k] = pk2(s * __ldg(&Whh[r0 * 4 + k]), s * __ldg(&Whh[(r0 + 1) * 4 + k]));
        bs[G] = pk2(s * (__ldg(&bih[r0])     + __ldg(&bhh[r0])),
                    s * (__ldg(&bih[r0 + 1]) + __ldg(&bhh[r0 + 1])));
    }

    float h0 = 0.f, h1 = 0.f, h2 = 0.f, h3 = 0.f;
    float c0 = 0.f, c1 = 0.f;

    const float4* xb   = reinterpret_cast<const float4*>(x + (size_t)b * (T_STEPS * 2));
    float4*       outp = g_h0 + b;

#pragma unroll 1
    for (int tt = 0; tt < T_STEPS / 2; ++tt) {
        float4 xv = __ldg(&xb[tt]);   // two timesteps of (x0, x1)
#pragma unroll
        for (int s = 0; s < 2; s++) {
            float x0 = s ? xv.z : xv.x;
            float x1 = s ? xv.w : xv.y;
            ull dx0 = pk2(x0, x0), dx1 = pk2(x1, x1);
            ull dh0 = pk2(h0, h0), dh1 = pk2(h1, h1);
            ull dh2 = pk2(h2, h2), dh3 = pk2(h3, h3);

            float y[8];
#pragma unroll
            for (int G = 0; G < 4; G++) {
                ull a = ffma2(wi[G][0], dx0, bs[G]);
                a = ffma2(wi[G][1], dx1, a);
                a = ffma2(wh[G][0], dh0, a);
                a = ffma2(wh[G][1], dh1, a);
                a = ffma2(wh[G][2], dh2, a);
                a = ffma2(wh[G][3], dh3, a);
                upk2(a, y[2 * G], y[2 * G + 1]);
            }

            float hA, hB;
            lstm_act(y, c0, c1, hA, hB);

            float oA = __shfl_xor_sync(0xFFFFFFFFu, hA, 1);
            float oB = __shfl_xor_sync(0xFFFFFFFFu, hB, 1);
            h0 = half ? oA : hA;
            h1 = half ? oB : hB;
            h2 = half ? hA : oA;
            h3 = half ? hB : oB;

            if (!half) *outp = make_float4(h0, h1, h2, h3);
            outp += B;
        }
    }
}

// ---------------------------------------------------------------------------
// Kernel B: layer 1 + fused readout.  h0 scratch -> out[b] = sigmoid(z)
// ---------------------------------------------------------------------------
__global__ __launch_bounds__(128, 4) void lstm_l1(
    const float* __restrict__ Wih,   // [16, 4]
    const float* __restrict__ Whh,   // [16, 4]
    const float* __restrict__ bih,
    const float* __restrict__ bhh,
    const float* __restrict__ Wout,  // [1, 200], col = t*4 + k
    const float* __restrict__ bout,
    float* __restrict__ out,
    int B)
{
    int g    = blockIdx.x * 128 + threadIdx.x;
    int b    = g >> 1;
    int half = g & 1;
    if (b >= B) return;

    ull wi[4][4], wh[4][4], bs[4];
#pragma unroll
    for (int G = 0; G < 4; G++) {
        int r0 = G * 4 + 2 * half;
        float s = gate_scale(G);
#pragma unroll
        for (int k = 0; k < 4; k++) {
            wi[G][k] = pk2(s * __ldg(&Wih[r0 * 4 + k]), s * __ldg(&Wih[(r0 + 1) * 4 + k]));
            wh[G][k] = pk2(s * __ldg(&Whh[r0 * 4 + k]), s * __ldg(&Whh[(r0 + 1) * 4 + k]));
        }
        bs[G] = pk2(s * (__ldg(&bih[r0])     + __ldg(&bhh[r0])),
                    s * (__ldg(&bih[r0 + 1]) + __ldg(&bhh[r0 + 1])));
    }

    float h0 = 0.f, h1 = 0.f, h2 = 0.f, h3 = 0.f;
    float c0 = 0.f, c1 = 0.f;
    float z = 0.f;

    const float4* hp  = g_h0 + b;
    const float2* wo2 = reinterpret_cast<const float2*>(Wout);

    float4 hin = __ldg(&hp[0]);
#pragma unroll 1
    for (int t = 0; t < T_STEPS; t++) {
        float4 hnx = (t + 1 < T_STEPS) ? __ldg(&hp[(size_t)(t + 1) * B])
                                       : make_float4(0.f, 0.f, 0.f, 0.f);

        ull dx0 = pk2(hin.x, hin.x), dx1 = pk2(hin.y, hin.y);
        ull dx2 = pk2(hin.z, hin.z), dx3 = pk2(hin.w, hin.w);
        ull dh0 = pk2(h0, h0), dh1 = pk2(h1, h1);
        ull dh2 = pk2(h2, h2), dh3 = pk2(h3, h3);

        float y[8];
#pragma unroll
        for (int G = 0; G < 4; G++) {
            ull a = ffma2(wi[G][0], dx0, bs[G]);
            a = ffma2(wi[G][1], dx1, a);
            a = ffma2(wi[G][2], dx2, a);
            a = ffma2(wi[G][3], dx3, a);
            a = ffma2(wh[G][0], dh0, a);
            a = ffma2(wh[G][1], dh1, a);
            a = ffma2(wh[G][2], dh2, a);
            a = ffma2(wh[G][3], dh3, a);
            upk2(a, y[2 * G], y[2 * G + 1]);
        }

        float hA, hB;
        lstm_act(y, c0, c1, hA, hB);

        // readout contribution of this thread's 2 units
        float2 w = __ldg(&wo2[t * 2 + half]);
        z = fmaf(hA, w.x, z);
        z = fmaf(hB, w.y, z);

        float oA = __shfl_xor_sync(0xFFFFFFFFu, hA, 1);
        float oB = __shfl_xor_sync(0xFFFFFFFFu, hB, 1);
        h0 = half ? oA : hA;
        h1 = half ? oB : hB;
        h2 = half ? hA : oA;
        h3 = half ? hB : oB;

        hin = hnx;
    }

    z += __shfl_xor_sync(0xFFFFFFFFu, z, 1);
    if (!half) out[b] = sigf(z + __ldg(&bout[0]));
}

// ---------------------------------------------------------------------------
extern "C" void kernel_launch(void* const* d_in, const int* in_sizes, int n_in,
                              void* d_out, int out_size)
{
    const float* x    = (const float*)d_in[0];
    const float* Wih0 = (const float*)d_in[1];
    const float* Whh0 = (const float*)d_in[2];
    const float* bih0 = (const float*)d_in[3];
    const float* bhh0 = (const float*)d_in[4];
    const float* Wih1 = (const float*)d_in[5];
    const float* Whh1 = (const float*)d_in[6];
    const float* bih1 = (const float*)d_in[7];
    const float* bhh1 = (const float*)d_in[8];
    const float* Wout = (const float*)d_in[9];
    const float* bout = (const float*)d_in[10];

    int B = in_sizes[0] / (T_STEPS * 2);
    if (B > B_MAX) B = B_MAX;
    int threads = 2 * B;
    int grid = (threads + 127) / 128;

    lstm_l0<<<grid, 128>>>(x, Wih0, Whh0, bih0, bhh0, B);
    lstm_l1<<<grid, 128>>>(Wih1, Whh1, bih1, bhh1, Wout, bout, (float*)d_out, B);
}

// round 3
// speedup vs baseline: 1.5633x; 1.4689x over previous
#include <cuda_runtime.h>

// ---------------------------------------------------------------------------
// R3: Fully fused 2-layer LSTM (H=4, I=2, T=50) + readout, single kernel.
//  - 4 threads per batch element; thread owns hidden unit u (both layers).
//  - Layer1 consumes layer0's h of the SAME timestep -> no 200MB scratch.
//  - All activations via tanh.approx.f32 (1 MUFU op each, vs 2 for ex2+rcp):
//    sigmoid(y) = 0.5 + 0.5*tanh(y/2), the 1/2 folded into weights/biases.
//    Cuts the chip MUFU floor from ~195us to ~123us.
//  - Gate MACs as packed fma.rn.f32x2 over gate-pairs (i,f) and (g,o).
//  - h broadcast across the 4-thread quad with 4 independent shfl.idx.
// ---------------------------------------------------------------------------

#define T_STEPS 50
typedef unsigned long long ull;

__device__ __forceinline__ ull pk2(float lo, float hi) {
    ull r; asm("mov.b64 %0, {%1, %2};" : "=l"(r) : "f"(lo), "f"(hi)); return r;
}
__device__ __forceinline__ void upk2(ull v, float& lo, float& hi) {
    asm("mov.b64 {%0, %1}, %2;" : "=f"(lo), "=f"(hi) : "l"(v));
}
__device__ __forceinline__ ull ffma2(ull a, ull b, ull c) {
    ull d; asm("fma.rn.f32x2 %0, %1, %2, %3;" : "=l"(d) : "l"(a), "l"(b), "l"(c));
    return d;
}
__device__ __forceinline__ float tanhap(float x) {
    float r; asm("tanh.approx.f32 %0, %1;" : "=f"(r) : "f"(x)); return r;
}
__device__ __forceinline__ float ex2f(float x) {
    float r; asm("ex2.approx.f32 %0, %1;" : "=f"(r) : "f"(x)); return r;
}
__device__ __forceinline__ float rcpf(float x) {
    float r; asm("rcp.approx.f32 %0, %1;" : "=f"(r) : "f"(x)); return r;
}

// Per-unit activation block: y pre-acts already scaled (sig rows by 0.5).
//   si = 0.5 + 0.5*tanh(yi) etc.; returns new h, updates c.
__device__ __forceinline__ float lstm_unit(float yi, float yf, float yg, float yo,
                                           float& c)
{
    float si = fmaf(0.5f, tanhap(yi), 0.5f);
    float sf = fmaf(0.5f, tanhap(yf), 0.5f);
    float tg = tanhap(yg);
    float so = fmaf(0.5f, tanhap(yo), 0.5f);
    c = fmaf(sf, c, si * tg);
    return so * tanhap(c);
}

__global__ __launch_bounds__(128, 5) void lstm_fused(
    const float* __restrict__ x,     // [B, T, 2]
    const float* __restrict__ Wih0,  // [16, 2]
    const float* __restrict__ Whh0,  // [16, 4]
    const float* __restrict__ bih0,
    const float* __restrict__ bhh0,
    const float* __restrict__ Wih1,  // [16, 4]
    const float* __restrict__ Whh1,  // [16, 4]
    const float* __restrict__ bih1,
    const float* __restrict__ bhh1,
    const float* __restrict__ Wout,  // [1, 200], col = t*4 + u
    const float* __restrict__ bout,
    float* __restrict__ out,
    int B)
{
    int g = blockIdx.x * 128 + threadIdx.x;
    int b = g >> 2;
    int u = g & 3;
    if (b >= B) return;
    int lane = threadIdx.x & 31;
    int base = lane & ~3;          // quad leader lane for shfl.idx

    // Gate rows for unit u: i=u, f=4+u, g=8+u, o=12+u.
    // Pair 0 = (i, f), scales (0.5, 0.5); pair 1 = (g, o), scales (1.0, 0.5).
    const int   rlo[2] = { u,      8 + u };
    const int   rhi[2] = { 4 + u, 12 + u };
    const float slo[2] = { 0.5f, 1.0f };
    const float shi[2] = { 0.5f, 0.5f };

    ull wi0[2][2], wh0[2][4], b0[2];
    ull wi1[2][4], wh1[2][4], b1[2];
#pragma unroll
    for (int p = 0; p < 2; p++) {
        int lo = rlo[p], hi = rhi[p];
        float sl = slo[p], sh = shi[p];
#pragma unroll
        for (int k = 0; k < 2; k++)
            wi0[p][k] = pk2(sl * __ldg(&Wih0[lo * 2 + k]), sh * __ldg(&Wih0[hi * 2 + k]));
#pragma unroll
        for (int k = 0; k < 4; k++) {
            wh0[p][k] = pk2(sl * __ldg(&Whh0[lo * 4 + k]), sh * __ldg(&Whh0[hi * 4 + k]));
            wi1[p][k] = pk2(sl * __ldg(&Wih1[lo * 4 + k]), sh * __ldg(&Wih1[hi * 4 + k]));
            wh1[p][k] = pk2(sl * __ldg(&Whh1[lo * 4 + k]), sh * __ldg(&Whh1[hi * 4 + k]));
        }
        b0[p] = pk2(sl * (__ldg(&bih0[lo]) + __ldg(&bhh0[lo])),
                    sh * (__ldg(&bih0[hi]) + __ldg(&bhh0[hi])));
        b1[p] = pk2(sl * (__ldg(&bih1[lo]) + __ldg(&bhh1[lo])),
                    sh * (__ldg(&bih1[hi]) + __ldg(&bhh1[hi])));
    }

    // State: own h per layer, c per layer, gathered broadcasts, readout acc.
    float hq0 = 0.f, hq1 = 0.f, cc0 = 0.f, cc1 = 0.f, z = 0.f;
    float g00 = 0.f, g01 = 0.f, g02 = 0.f, g03 = 0.f;   // layer0 h (all units)
    float g10 = 0.f, g11 = 0.f, g12 = 0.f, g13 = 0.f;   // layer1 h (all units)

    const float4* xb = reinterpret_cast<const float4*>(x + (size_t)b * (T_STEPS * 2));

#pragma unroll 1
    for (int tt = 0; tt < T_STEPS / 2; ++tt) {
        float4 xv = __ldg(&xb[tt]);   // 2 timesteps of (x0, x1), quad-broadcast
#pragma unroll
        for (int s = 0; s < 2; s++) {
            // ---- layer 0 ----
            float x0 = s ? xv.z : xv.x;
            float x1 = s ? xv.w : xv.y;
            ull dx0 = pk2(x0, x0), dx1 = pk2(x1, x1);
            ull dh0 = pk2(g00, g00), dh1 = pk2(g01, g01);
            ull dh2 = pk2(g02, g02), dh3 = pk2(g03, g03);

            ull a0 = ffma2(wi0[0][0], dx0, b0[0]);
            ull a1 = ffma2(wi0[1][0], dx0, b0[1]);
            a0 = ffma2(wi0[0][1], dx1, a0);
            a1 = ffma2(wi0[1][1], dx1, a1);
            a0 = ffma2(wh0[0][0], dh0, a0);  a1 = ffma2(wh0[1][0], dh0, a1);
            a0 = ffma2(wh0[0][1], dh1, a0);  a1 = ffma2(wh0[1][1], dh1, a1);
            a0 = ffma2(wh0[0][2], dh2, a0);  a1 = ffma2(wh0[1][2], dh2, a1);
            a0 = ffma2(wh0[0][3], dh3, a0);  a1 = ffma2(wh0[1][3], dh3, a1);

            float yi, yf, yg, yo;
            upk2(a0, yi, yf);
            upk2(a1, yg, yo);
            hq0 = lstm_unit(yi, yf, yg, yo, cc0);

            // broadcast layer0 h across quad (4 independent shfl.idx)
            g00 = __shfl_sync(0xFFFFFFFFu, hq0, base + 0);
            g01 = __shfl_sync(0xFFFFFFFFu, hq0, base + 1);
            g02 = __shfl_sync(0xFFFFFFFFu, hq0, base + 2);
            g03 = __shfl_sync(0xFFFFFFFFu, hq0, base + 3);

            // ---- layer 1 (input = layer0 h of this step) ----
            ull e0 = pk2(g00, g00), e1 = pk2(g01, g01);
            ull e2 = pk2(g02, g02), e3 = pk2(g03, g03);
            ull f0 = pk2(g10, g10), f1 = pk2(g11, g11);
            ull f2 = pk2(g12, g12), f3 = pk2(g13, g13);

            ull m0 = ffma2(wi1[0][0], e0, b1[0]);
            ull m1 = ffma2(wi1[1][0], e0, b1[1]);
            m0 = ffma2(wi1[0][1], e1, m0);  m1 = ffma2(wi1[1][1], e1, m1);
            m0 = ffma2(wi1[0][2], e2, m0);  m1 = ffma2(wi1[1][2], e2, m1);
            m0 = ffma2(wi1[0][3], e3, m0);  m1 = ffma2(wi1[1][3], e3, m1);
            m0 = ffma2(wh1[0][0], f0, m0);  m1 = ffma2(wh1[1][0], f0, m1);
            m0 = ffma2(wh1[0][1], f1, m0);  m1 = ffma2(wh1[1][1], f1, m1);
            m0 = ffma2(wh1[0][2], f2, m0);  m1 = ffma2(wh1[1][2], f2, m1);
            m0 = ffma2(wh1[0][3], f3, m0);  m1 = ffma2(wh1[1][3], f3, m1);

            float zi, zf, zg, zo;
            upk2(m0, zi, zf);
            upk2(m1, zg, zo);
            hq1 = lstm_unit(zi, zf, zg, zo, cc1);

            // readout contribution of own unit (uniform broadcast load)
            int t = 2 * tt + s;
            z = fmaf(hq1, __ldg(&Wout[t * 4 + u]), z);

            // broadcast layer1 h for next step's recurrence
            g10 = __shfl_sync(0xFFFFFFFFu, hq1, base + 0);
            g11 = __shfl_sync(0xFFFFFFFFu, hq1, base + 1);
            g12 = __shfl_sync(0xFFFFFFFFu, hq1, base + 2);
            g13 = __shfl_sync(0xFFFFFFFFu, hq1, base + 3);
        }
    }

    // quad reduction of z, accurate output sigmoid
    z += __shfl_xor_sync(0xFFFFFFFFu, z, 1);
    z += __shfl_xor_sync(0xFFFFFFFFu, z, 2);
    if (u == 0)
        out[b] = rcpf(1.0f + ex2f(-1.442695040888963f * (z + __ldg(&bout[0]))));
}

// ---------------------------------------------------------------------------
extern "C" void kernel_launch(void* const* d_in, const int* in_sizes, int n_in,
                              void* d_out, int out_size)
{
    const float* x    = (const float*)d_in[0];
    const float* Wih0 = (const float*)d_in[1];
    const float* Whh0 = (const float*)d_in[2];
    const float* bih0 = (const float*)d_in[3];
    const float* bhh0 = (const float*)d_in[4];
    const float* Wih1 = (const float*)d_in[5];
    const float* Whh1 = (const float*)d_in[6];
    const float* bih1 = (const float*)d_in[7];
    const float* bhh1 = (const float*)d_in[8];
    const float* Wout = (const float*)d_in[9];
    const float* bout = (const float*)d_in[10];

    int B = in_sizes[0] / (T_STEPS * 2);
    int threads = 4 * B;
    int grid = (threads + 127) / 128;

    lstm_fused<<<grid, 128>>>(x, Wih0, Whh0, bih0, bhh0,
                              Wih1, Whh1, bih1, bhh1,
                              Wout, bout, (float*)d_out, B);
}

// round 4
// speedup vs baseline: 1.9308x; 1.2351x over previous
#include <cuda_runtime.h>

// ---------------------------------------------------------------------------
// R4: Fused 2-layer LSTM (H=4, I=2, T=50) + readout, single kernel,
//     TWO batch elements per thread (quad of 4 lanes owns elements 2q,2q+1).
// R3 was latency-bound (issue 41%, no pipe >39%): the ~95-cycle serial chain
// (FFMA2 chain -> tanh chain -> shfl) per step had too little cover at 4.5
// warps/SMSP. Weights are identical across elements, so a second element
// costs only ~26 state registers while doubling independent ILP.
//  - sigmoid via tanh.approx (scale 0.5 folded into weights/biases)
//  - gate MACs as packed fma.rn.f32x2 over gate-pairs (i,f) and (g,o)
//  - h broadcast across the quad with shfl.idx (8 per layer-step, 2 elems)
//  - coalesced float2 output store per quad
// ---------------------------------------------------------------------------

#define T_STEPS 50
typedef unsigned long long ull;

__device__ __forceinline__ ull pk2(float lo, float hi) {
    ull r; asm("mov.b64 %0, {%1, %2};" : "=l"(r) : "f"(lo), "f"(hi)); return r;
}
__device__ __forceinline__ void upk2(ull v, float& lo, float& hi) {
    asm("mov.b64 {%0, %1}, %2;" : "=f"(lo), "=f"(hi) : "l"(v));
}
__device__ __forceinline__ ull ffma2(ull a, ull b, ull c) {
    ull d; asm("fma.rn.f32x2 %0, %1, %2, %3;" : "=l"(d) : "l"(a), "l"(b), "l"(c));
    return d;
}
__device__ __forceinline__ float tanhap(float x) {
    float r; asm("tanh.approx.f32 %0, %1;" : "=f"(r) : "f"(x)); return r;
}
__device__ __forceinline__ float ex2f(float x) {
    float r; asm("ex2.approx.f32 %0, %1;" : "=f"(r) : "f"(x)); return r;
}
__device__ __forceinline__ float rcpf(float x) {
    float r; asm("rcp.approx.f32 %0, %1;" : "=f"(r) : "f"(x)); return r;
}

// y pre-acts already scaled (sigmoid rows by 0.5): si = 0.5 + 0.5*tanh(yi).
__device__ __forceinline__ float lstm_unit(float yi, float yf, float yg, float yo,
                                           float& c)
{
    float si = fmaf(0.5f, tanhap(yi), 0.5f);
    float sf = fmaf(0.5f, tanhap(yf), 0.5f);
    float tg = tanhap(yg);
    float so = fmaf(0.5f, tanhap(yo), 0.5f);
    c = fmaf(sf, c, si * tg);
    return so * tanhap(c);
}

__global__ __launch_bounds__(128, 4) void lstm_fused2(
    const float* __restrict__ x,     // [B, T, 2]
    const float* __restrict__ Wih0,  // [16, 2]
    const float* __restrict__ Whh0,  // [16, 4]
    const float* __restrict__ bih0,
    const float* __restrict__ bhh0,
    const float* __restrict__ Wih1,  // [16, 4]
    const float* __restrict__ Whh1,  // [16, 4]
    const float* __restrict__ bih1,
    const float* __restrict__ bhh1,
    const float* __restrict__ Wout,  // [1, 200], col = t*4 + u
    const float* __restrict__ bout,
    float* __restrict__ out,
    int B)
{
    int g = blockIdx.x * 128 + threadIdx.x;
    int q = g >> 2;            // quad index: owns elements 2q, 2q+1
    int u = g & 3;             // hidden unit owned by this lane
    int eA = 2 * q;
    if (eA >= B) return;
    int base = (threadIdx.x & 31) & ~3;   // quad leader lane

    // Gate rows for unit u: i=u, f=4+u, g=8+u, o=12+u.
    // Pair 0 = (i,f) scales (.5,.5); pair 1 = (g,o) scales (1,.5).
    const int   rlo[2] = { u,      8 + u };
    const int   rhi[2] = { 4 + u, 12 + u };
    const float slo[2] = { 0.5f, 1.0f };
    const float shi[2] = { 0.5f, 0.5f };

    ull wi0[2][2], wh0[2][4], b0[2];
    ull wi1[2][4], wh1[2][4], b1[2];
#pragma unroll
    for (int p = 0; p < 2; p++) {
        int lo = rlo[p], hi = rhi[p];
        float sl = slo[p], sh = shi[p];
#pragma unroll
        for (int k = 0; k < 2; k++)
            wi0[p][k] = pk2(sl * __ldg(&Wih0[lo * 2 + k]), sh * __ldg(&Wih0[hi * 2 + k]));
#pragma unroll
        for (int k = 0; k < 4; k++) {
            wh0[p][k] = pk2(sl * __ldg(&Whh0[lo * 4 + k]), sh * __ldg(&Whh0[hi * 4 + k]));
            wi1[p][k] = pk2(sl * __ldg(&Wih1[lo * 4 + k]), sh * __ldg(&Wih1[hi * 4 + k]));
            wh1[p][k] = pk2(sl * __ldg(&Whh1[lo * 4 + k]), sh * __ldg(&Whh1[hi * 4 + k]));
        }
        b0[p] = pk2(sl * (__ldg(&bih0[lo]) + __ldg(&bhh0[lo])),
                    sh * (__ldg(&bih0[hi]) + __ldg(&bhh0[hi])));
        b1[p] = pk2(sl * (__ldg(&bih1[lo]) + __ldg(&bhh1[lo])),
                    sh * (__ldg(&bih1[hi]) + __ldg(&bhh1[hi])));
    }

    // Per-element state (e = 0 -> eA, e = 1 -> eB)
    float cc0[2] = {0.f, 0.f}, cc1[2] = {0.f, 0.f}, z[2] = {0.f, 0.f};
    float g0[2][4] = {{0.f}}, g1[2][4] = {{0.f}};

    const float4* xbA = reinterpret_cast<const float4*>(x + (size_t)eA * (T_STEPS * 2));
    const float4* xbB = reinterpret_cast<const float4*>(x + (size_t)(eA + 1) * (T_STEPS * 2));

#pragma unroll 1
    for (int tt = 0; tt < T_STEPS / 2; ++tt) {
        float4 xv[2];
        xv[0] = __ldg(&xbA[tt]);
        xv[1] = __ldg(&xbB[tt]);
        float wo = __ldg(&Wout[(2 * tt) * 4 + u]);       // readout weights for
        float wo2 = __ldg(&Wout[(2 * tt + 1) * 4 + u]);  // both sub-steps

#pragma unroll
        for (int s = 0; s < 2; s++) {
            float hq0[2], hq1[2];

            // ---- layer 0, both elements (independent chains) ----
#pragma unroll
            for (int e = 0; e < 2; e++) {
                float x0 = s ? xv[e].z : xv[e].x;
                float x1 = s ? xv[e].w : xv[e].y;
                ull dx0 = pk2(x0, x0), dx1 = pk2(x1, x1);
                ull dh0 = pk2(g0[e][0], g0[e][0]), dh1 = pk2(g0[e][1], g0[e][1]);
                ull dh2 = pk2(g0[e][2], g0[e][2]), dh3 = pk2(g0[e][3], g0[e][3]);

                ull a0 = ffma2(wi0[0][0], dx0, b0[0]);
                ull a1 = ffma2(wi0[1][0], dx0, b0[1]);
                a0 = ffma2(wi0[0][1], dx1, a0);  a1 = ffma2(wi0[1][1], dx1, a1);
                a0 = ffma2(wh0[0][0], dh0, a0);  a1 = ffma2(wh0[1][0], dh0, a1);
                a0 = ffma2(wh0[0][1], dh1, a0);  a1 = ffma2(wh0[1][1], dh1, a1);
                a0 = ffma2(wh0[0][2], dh2, a0);  a1 = ffma2(wh0[1][2], dh2, a1);
                a0 = ffma2(wh0[0][3], dh3, a0);  a1 = ffma2(wh0[1][3], dh3, a1);

                float yi, yf, yg, yo;
                upk2(a0, yi, yf);
                upk2(a1, yg, yo);
                hq0[e] = lstm_unit(yi, yf, yg, yo, cc0[e]);
            }

            // broadcast layer0 h across quad, both elements
#pragma unroll
            for (int e = 0; e < 2; e++) {
                g0[e][0] = __shfl_sync(0xFFFFFFFFu, hq0[e], base + 0);
                g0[e][1] = __shfl_sync(0xFFFFFFFFu, hq0[e], base + 1);
                g0[e][2] = __shfl_sync(0xFFFFFFFFu, hq0[e], base + 2);
                g0[e][3] = __shfl_sync(0xFFFFFFFFu, hq0[e], base + 3);
            }

            // ---- layer 1, both elements ----
#pragma unroll
            for (int e = 0; e < 2; e++) {
                ull e0 = pk2(g0[e][0], g0[e][0]), e1 = pk2(g0[e][1], g0[e][1]);
                ull e2 = pk2(g0[e][2], g0[e][2]), e3 = pk2(g0[e][3], g0[e][3]);
                ull f0 = pk2(g1[e][0], g1[e][0]), f1 = pk2(g1[e][1], g1[e][1]);
                ull f2 = pk2(g1[e][2], g1[e][2]), f3 = pk2(g1[e][3], g1[e][3]);

                ull m0 = ffma2(wi1[0][0], e0, b1[0]);
                ull m1 = ffma2(wi1[1][0], e0, b1[1]);
                m0 = ffma2(wi1[0][1], e1, m0);  m1 = ffma2(wi1[1][1], e1, m1);
                m0 = ffma2(wi1[0][2], e2, m0);  m1 = ffma2(wi1[1][2], e2, m1);
                m0 = ffma2(wi1[0][3], e3, m0);  m1 = ffma2(wi1[1][3], e3, m1);
                m0 = ffma2(wh1[0][0], f0, m0);  m1 = ffma2(wh1[1][0], f0, m1);
                m0 = ffma2(wh1[0][1], f1, m0);  m1 = ffma2(wh1[1][1], f1, m1);
                m0 = ffma2(wh1[0][2], f2, m0);  m1 = ffma2(wh1[1][2], f2, m1);
                m0 = ffma2(wh1[0][3], f3, m0);  m1 = ffma2(wh1[1][3], f3, m1);

                float zi, zf, zg, zo;
                upk2(m0, zi, zf);
                upk2(m1, zg, zo);
                hq1[e] = lstm_unit(zi, zf, zg, zo, cc1[e]);

                // readout contribution of this thread's unit
                z[e] = fmaf(hq1[e], s ? wo2 : wo, z[e]);
            }

            // broadcast layer1 h for next step's recurrence
#pragma unroll
            for (int e = 0; e < 2; e++) {
                g1[e][0] = __shfl_sync(0xFFFFFFFFu, hq1[e], base + 0);
                g1[e][1] = __shfl_sync(0xFFFFFFFFu, hq1[e], base + 1);
                g1[e][2] = __shfl_sync(0xFFFFFFFFu, hq1[e], base + 2);
                g1[e][3] = __shfl_sync(0xFFFFFFFFu, hq1[e], base + 3);
            }
        }
    }

    // quad reduction of both readouts; all lanes get the sums
    float zA = z[0], zB = z[1];
    zA += __shfl_xor_sync(0xFFFFFFFFu, zA, 1);
    zA += __shfl_xor_sync(0xFFFFFFFFu, zA, 2);
    zB += __shfl_xor_sync(0xFFFFFFFFu, zB, 1);
    zB += __shfl_xor_sync(0xFFFFFFFFu, zB, 2);

    if (u == 0) {
        float bo = __ldg(&bout[0]);
        float2 r;
        r.x = rcpf(1.0f + ex2f(-1.442695040888963f * (zA + bo)));
        r.y = rcpf(1.0f + ex2f(-1.442695040888963f * (zB + bo)));
        *reinterpret_cast<float2*>(out + eA) = r;   // eA even -> 8B aligned
    }
}

// ---------------------------------------------------------------------------
extern "C" void kernel_launch(void* const* d_in, const int* in_sizes, int n_in,
                              void* d_out, int out_size)
{
    const float* x    = (const float*)d_in[0];
    const float* Wih0 = (const float*)d_in[1];
    const float* Whh0 = (const float*)d_in[2];
    const float* bih0 = (const float*)d_in[3];
    const float* bhh0 = (const float*)d_in[4];
    const float* Wih1 = (const float*)d_in[5];
    const float* Whh1 = (const float*)d_in[6];
    const float* bih1 = (const float*)d_in[7];
    const float* bhh1 = (const float*)d_in[8];
    const float* Wout = (const float*)d_in[9];
    const float* bout = (const float*)d_in[10];

    int B = in_sizes[0] / (T_STEPS * 2);
    int threads = 2 * B;               // 4 lanes per 2 elements
    int grid = (threads + 127) / 128;

    lstm_fused2<<<grid, 128>>>(x, Wih0, Whh0, bih0, bhh0,
                               Wih1, Whh1, bih1, bhh1,
                               Wout, bout, (float*)d_out, B);
}

// round 5
// speedup vs baseline: 1.9865x; 1.0288x over previous
#include <cuda_runtime.h>

// ---------------------------------------------------------------------------
// R5: Fused 2-layer LSTM (H=4, I=2, T=50) + readout, single kernel,
//     FOUR batch elements per thread (quad of 4 lanes owns elements 4q..4q+3).
// R4 remained latency-bound (issue 47%, all pipes <50%). Weights are uniform
// across elements so ILP 2->4 costs only ~+22 state regs while doubling the
// number of independent recurrence chains per SMSP (7.4 -> 12).
// Layer1 gate accumulation is reordered recurrent-terms-first so the fresh
// layer0 shfl-broadcast results are consumed at the END of an 8-FFMA2 chain,
// burying the 26-cycle shfl latency.
//  - sigmoid via tanh.approx (0.5 scale folded into weights/biases)
//  - gate MACs as packed fma.rn.f32x2 over gate-pairs (i,f) and (g,o)
//  - coalesced float4 output store per quad
// ---------------------------------------------------------------------------

#define T_STEPS 50
typedef unsigned long long ull;

__device__ __forceinline__ ull pk2(float lo, float hi) {
    ull r; asm("mov.b64 %0, {%1, %2};" : "=l"(r) : "f"(lo), "f"(hi)); return r;
}
__device__ __forceinline__ void upk2(ull v, float& lo, float& hi) {
    asm("mov.b64 {%0, %1}, %2;" : "=f"(lo), "=f"(hi) : "l"(v));
}
__device__ __forceinline__ ull ffma2(ull a, ull b, ull c) {
    ull d; asm("fma.rn.f32x2 %0, %1, %2, %3;" : "=l"(d) : "l"(a), "l"(b), "l"(c));
    return d;
}
__device__ __forceinline__ float tanhap(float x) {
    float r; asm("tanh.approx.f32 %0, %1;" : "=f"(r) : "f"(x)); return r;
}
__device__ __forceinline__ float ex2f(float x) {
    float r; asm("ex2.approx.f32 %0, %1;" : "=f"(r) : "f"(x)); return r;
}
__device__ __forceinline__ float rcpf(float x) {
    float r; asm("rcp.approx.f32 %0, %1;" : "=f"(r) : "f"(x)); return r;
}

// y pre-acts already scaled (sigmoid rows by 0.5): si = 0.5 + 0.5*tanh(yi).
__device__ __forceinline__ float lstm_unit(float yi, float yf, float yg, float yo,
                                           float& c)
{
    float si = fmaf(0.5f, tanhap(yi), 0.5f);
    float sf = fmaf(0.5f, tanhap(yf), 0.5f);
    float tg = tanhap(yg);
    float so = fmaf(0.5f, tanhap(yo), 0.5f);
    c = fmaf(sf, c, si * tg);
    return so * tanhap(c);
}

#define NE 4   // batch elements per thread

__global__ __launch_bounds__(128, 3) void lstm_fused4(
    const float* __restrict__ x,     // [B, T, 2]
    const float* __restrict__ Wih0,  // [16, 2]
    const float* __restrict__ Whh0,  // [16, 4]
    const float* __restrict__ bih0,
    const float* __restrict__ bhh0,
    const float* __restrict__ Wih1,  // [16, 4]
    const float* __restrict__ Whh1,  // [16, 4]
    const float* __restrict__ bih1,
    const float* __restrict__ bhh1,
    const float* __restrict__ Wout,  // [1, 200], col = t*4 + u
    const float* __restrict__ bout,
    float* __restrict__ out,
    int B)
{
    int g = blockIdx.x * 128 + threadIdx.x;
    int q = g >> 2;            // quad index: owns elements NE*q .. NE*q+3
    int u = g & 3;             // hidden unit owned by this lane
    int eA = NE * q;
    if (eA >= B) return;
    int base = (threadIdx.x & 31) & ~3;   // quad leader lane

    // Gate rows for unit u: i=u, f=4+u, g=8+u, o=12+u.
    // Pair 0 = (i,f) scales (.5,.5); pair 1 = (g,o) scales (1,.5).
    const int   rlo[2] = { u,      8 + u };
    const int   rhi[2] = { 4 + u, 12 + u };
    const float slo[2] = { 0.5f, 1.0f };
    const float shi[2] = { 0.5f, 0.5f };

    ull wi0[2][2], wh0[2][4], b0[2];
    ull wi1[2][4], wh1[2][4], b1[2];
#pragma unroll
    for (int p = 0; p < 2; p++) {
        int lo = rlo[p], hi = rhi[p];
        float sl = slo[p], sh = shi[p];
#pragma unroll
        for (int k = 0; k < 2; k++)
            wi0[p][k] = pk2(sl * __ldg(&Wih0[lo * 2 + k]), sh * __ldg(&Wih0[hi * 2 + k]));
#pragma unroll
        for (int k = 0; k < 4; k++) {
            wh0[p][k] = pk2(sl * __ldg(&Whh0[lo * 4 + k]), sh * __ldg(&Whh0[hi * 4 + k]));
            wi1[p][k] = pk2(sl * __ldg(&Wih1[lo * 4 + k]), sh * __ldg(&Wih1[hi * 4 + k]));
            wh1[p][k] = pk2(sl * __ldg(&Whh1[lo * 4 + k]), sh * __ldg(&Whh1[hi * 4 + k]));
        }
        b0[p] = pk2(sl * (__ldg(&bih0[lo]) + __ldg(&bhh0[lo])),
                    sh * (__ldg(&bih0[hi]) + __ldg(&bhh0[hi])));
        b1[p] = pk2(sl * (__ldg(&bih1[lo]) + __ldg(&bhh1[lo])),
                    sh * (__ldg(&bih1[hi]) + __ldg(&bhh1[hi])));
    }

    // Per-element state
    float cc0[NE], cc1[NE], z[NE];
    float g0[NE][4], g1[NE][4];
#pragma unroll
    for (int e = 0; e < NE; e++) {
        cc0[e] = cc1[e] = z[e] = 0.f;
#pragma unroll
        for (int k = 0; k < 4; k++) { g0[e][k] = 0.f; g1[e][k] = 0.f; }
    }

    const float4* xb[NE];
#pragma unroll
    for (int e = 0; e < NE; e++)
        xb[e] = reinterpret_cast<const float4*>(x + (size_t)(eA + e) * (T_STEPS * 2));

#pragma unroll 1
    for (int tt = 0; tt < T_STEPS / 2; ++tt) {
        float4 xv[NE];
#pragma unroll
        for (int e = 0; e < NE; e++) xv[e] = __ldg(&xb[e][tt]);
        float wo  = __ldg(&Wout[(2 * tt) * 4 + u]);
        float wo2 = __ldg(&Wout[(2 * tt + 1) * 4 + u]);

#pragma unroll
        for (int s = 0; s < 2; s++) {
            float hq0[NE], hq1[NE];

            // ---- layer 0, all elements (independent chains) ----
#pragma unroll
            for (int e = 0; e < NE; e++) {
                float x0 = s ? xv[e].z : xv[e].x;
                float x1 = s ? xv[e].w : xv[e].y;
                ull dh0 = pk2(g0[e][0], g0[e][0]), dh1 = pk2(g0[e][1], g0[e][1]);
                ull dh2 = pk2(g0[e][2], g0[e][2]), dh3 = pk2(g0[e][3], g0[e][3]);
                ull dx0 = pk2(x0, x0), dx1 = pk2(x1, x1);

                ull a0 = ffma2(wh0[0][0], dh0, b0[0]);
                ull a1 = ffma2(wh0[1][0], dh0, b0[1]);
                a0 = ffma2(wh0[0][1], dh1, a0);  a1 = ffma2(wh0[1][1], dh1, a1);
                a0 = ffma2(wh0[0][2], dh2, a0);  a1 = ffma2(wh0[1][2], dh2, a1);
                a0 = ffma2(wh0[0][3], dh3, a0);  a1 = ffma2(wh0[1][3], dh3, a1);
                a0 = ffma2(wi0[0][0], dx0, a0);  a1 = ffma2(wi0[1][0], dx0, a1);
                a0 = ffma2(wi0[0][1], dx1, a0);  a1 = ffma2(wi0[1][1], dx1, a1);

                float yi, yf, yg, yo;
                upk2(a0, yi, yf);
                upk2(a1, yg, yo);
                hq0[e] = lstm_unit(yi, yf, yg, yo, cc0[e]);
            }

            // broadcast layer0 h across quad
#pragma unroll
            for (int e = 0; e < NE; e++) {
                g0[e][0] = __shfl_sync(0xFFFFFFFFu, hq0[e], base + 0);
                g0[e][1] = __shfl_sync(0xFFFFFFFFu, hq0[e], base + 1);
                g0[e][2] = __shfl_sync(0xFFFFFFFFu, hq0[e], base + 2);
                g0[e][3] = __shfl_sync(0xFFFFFFFFu, hq0[e], base + 3);
            }

            // ---- layer 1: recurrent (old g1) terms FIRST, fresh g0 LAST ----
#pragma unroll
            for (int e = 0; e < NE; e++) {
                ull f0 = pk2(g1[e][0], g1[e][0]), f1 = pk2(g1[e][1], g1[e][1]);
                ull f2 = pk2(g1[e][2], g1[e][2]), f3 = pk2(g1[e][3], g1[e][3]);

                ull m0 = ffma2(wh1[0][0], f0, b1[0]);
                ull m1 = ffma2(wh1[1][0], f0, b1[1]);
                m0 = ffma2(wh1[0][1], f1, m0);  m1 = ffma2(wh1[1][1], f1, m1);
                m0 = ffma2(wh1[0][2], f2, m0);  m1 = ffma2(wh1[1][2], f2, m1);
                m0 = ffma2(wh1[0][3], f3, m0);  m1 = ffma2(wh1[1][3], f3, m1);

                ull e0 = pk2(g0[e][0], g0[e][0]), e1 = pk2(g0[e][1], g0[e][1]);
                ull e2 = pk2(g0[e][2], g0[e][2]), e3 = pk2(g0[e][3], g0[e][3]);
                m0 = ffma2(wi1[0][0], e0, m0);  m1 = ffma2(wi1[1][0], e0, m1);
                m0 = ffma2(wi1[0][1], e1, m0);  m1 = ffma2(wi1[1][1], e1, m1);
                m0 = ffma2(wi1[0][2], e2, m0);  m1 = ffma2(wi1[1][2], e2, m1);
                m0 = ffma2(wi1[0][3], e3, m0);  m1 = ffma2(wi1[1][3], e3, m1);

                float zi, zf, zg, zo;
                upk2(m0, zi, zf);
                upk2(m1, zg, zo);
                hq1[e] = lstm_unit(zi, zf, zg, zo, cc1[e]);

                z[e] = fmaf(hq1[e], s ? wo2 : wo, z[e]);
            }

            // broadcast layer1 h for next step's recurrence
#pragma unroll
            for (int e = 0; e < NE; e++) {
                g1[e][0] = __shfl_sync(0xFFFFFFFFu, hq1[e], base + 0);
                g1[e][1] = __shfl_sync(0xFFFFFFFFu, hq1[e], base + 1);
                g1[e][2] = __shfl_sync(0xFFFFFFFFu, hq1[e], base + 2);
                g1[e][3] = __shfl_sync(0xFFFFFFFFu, hq1[e], base + 3);
            }
        }
    }

    // quad reduction of readouts; lane u==0 stores a coalesced float4
#pragma unroll
    for (int e = 0; e < NE; e++) {
        z[e] += __shfl_xor_sync(0xFFFFFFFFu, z[e], 1);
        z[e] += __shfl_xor_sync(0xFFFFFFFFu, z[e], 2);
    }
    if (u == 0) {
        float bo = __ldg(&bout[0]);
        float4 r;
        r.x = rcpf(1.0f + ex2f(-1.442695040888963f * (z[0] + bo)));
        r.y = rcpf(1.0f + ex2f(-1.442695040888963f * (z[1] + bo)));
        r.z = rcpf(1.0f + ex2f(-1.442695040888963f * (z[2] + bo)));
        r.w = rcpf(1.0f + ex2f(-1.442695040888963f * (z[3] + bo)));
        *reinterpret_cast<float4*>(out + eA) = r;   // eA % 4 == 0 -> aligned
    }
}

// ---------------------------------------------------------------------------
extern "C" void kernel_launch(void* const* d_in, const int* in_sizes, int n_in,
                              void* d_out, int out_size)
{
    const float* x    = (const float*)d_in[0];
    const float* Wih0 = (const float*)d_in[1];
    const float* Whh0 = (const float*)d_in[2];
    const float* bih0 = (const float*)d_in[3];
    const float* bhh0 = (const float*)d_in[4];
    const float* Wih1 = (const float*)d_in[5];
    const float* Whh1 = (const float*)d_in[6];
    const float* bih1 = (const float*)d_in[7];
    const float* bhh1 = (const float*)d_in[8];
    const float* Wout = (const float*)d_in[9];
    const float* bout = (const float*)d_in[10];

    int B = in_sizes[0] / (T_STEPS * 2);
    int threads = B;                   // 4 lanes per 4 elements
    int grid = (threads + 127) / 128;

    lstm_fused4<<<grid, 128>>>(x, Wih0, Whh0, bih0, bhh0,
                               Wih1, Whh1, bih1, bhh1,
                               Wout, bout, (float*)d_out, B);
}